// round 2
// baseline (speedup 1.0000x reference)
#include <cuda_runtime.h>

#define N_NODES 100000
#define N_EDGES 1000000
#define F 64
#define G 128

// ---------------- scratch (static device globals; no allocation) ----------
// __align__(16): these are accessed as float4 / red.v4.f32 (128-bit ops trap
// on misalignment).
__device__ __align__(16) float d_XR[(size_t)N_NODES * F];  // x @ w1_rel.T
__device__ __align__(16) float d_H [(size_t)N_NODES * F];  // x@w1_root.T + b1, then += aggr
__device__ float d_a [N_NODES];               // relu(h1) . v_rel
__device__ float d_S [N_NODES];               // per-node scalar h2 . w_lin
__device__ float d_vrel[F];
__device__ float d_vroot[F];
__device__ float d_c2;
__device__ float d_gsum[G];
__device__ float d_gcnt[G];

// ---------------- init: collapse layer2+readout weights, zero pools -------
__global__ void k_init(const float* __restrict__ w2rel,
                       const float* __restrict__ w2root,
                       const float* __restrict__ b2,
                       const float* __restrict__ wlin) {
    int t = threadIdx.x;  // 128 threads
    if (t < G) { d_gsum[t] = 0.f; d_gcnt[t] = 0.f; }
    if (t < F) {
        float vr = 0.f, vo = 0.f;
        #pragma unroll 8
        for (int h = 0; h < F; h++) {
            float wl = wlin[h];
            vr += wl * w2rel[h * F + t];
            vo += wl * w2root[h * F + t];
        }
        d_vrel[t] = vr; d_vroot[t] = vo;
    }
    if (t == 0) {
        float c = 0.f;
        for (int h = 0; h < F; h++) c += wlin[h] * b2[h];
        d_c2 = c;
    }
}

// ---------------- kernel A: XR = x@w1_rel.T ; H = x@w1_root.T + b1 --------
#define TN 48      // nodes per tile (shared fits <48KB static)
#define NPT 12     // nodes per thread
#define WPAD 68    // padded row stride (floats) -> conflict-free LDS.128

__global__ __launch_bounds__(256, 4)
void k_gemm1(const float* __restrict__ x, const float* __restrict__ w1rel,
             const float* __restrict__ b1, const float* __restrict__ w1root) {
    __shared__ float sWr[F * WPAD];
    __shared__ float sWo[F * WPAD];
    __shared__ float sX[TN * F];
    __shared__ float sB1[F];

    int tid = threadIdx.x;
    for (int i = tid; i < F * F; i += 256) {
        int j = i >> 6, k = i & 63;
        sWr[j * WPAD + k] = w1rel[i];
        sWo[j * WPAD + k] = w1root[i];
    }
    if (tid < F) sB1[tid] = b1[tid];

    int oc = tid & 63;        // output column
    int ns = tid >> 6;        // node sub-lane 0..3
    float4* xs4 = reinterpret_cast<float4*>(sX);
    const int ntiles = (N_NODES + TN - 1) / TN;

    for (int tile = blockIdx.x; tile < ntiles; tile += gridDim.x) {
        int nbase  = tile * TN;
        int nvalid = min(TN, N_NODES - nbase);
        __syncthreads();   // sX reuse + first-iter weight visibility
        const float4* xg = reinterpret_cast<const float4*>(x + (size_t)nbase * F);
        #pragma unroll
        for (int i = 0; i < 3; i++) {            // 768 float4 / 256 threads
            int idx  = tid + i * 256;
            int node = idx >> 4;
            float4 v = make_float4(0.f, 0.f, 0.f, 0.f);
            if (node < nvalid) v = xg[idx];
            xs4[idx] = v;
        }
        __syncthreads();

        float accR[NPT], accO[NPT];
        #pragma unroll
        for (int i = 0; i < NPT; i++) { accR[i] = 0.f; accO[i] = 0.f; }

        #pragma unroll
        for (int k4 = 0; k4 < 16; k4++) {
            float4 wr = *reinterpret_cast<const float4*>(&sWr[oc * WPAD + k4 * 4]);
            float4 wo = *reinterpret_cast<const float4*>(&sWo[oc * WPAD + k4 * 4]);
            #pragma unroll
            for (int i = 0; i < NPT; i++) {
                float4 xv = xs4[(ns + i * 4) * 16 + k4];
                accR[i] += xv.x * wr.x + xv.y * wr.y + xv.z * wr.z + xv.w * wr.w;
                accO[i] += xv.x * wo.x + xv.y * wo.y + xv.z * wo.z + xv.w * wo.w;
            }
        }
        float bb = sB1[oc];
        #pragma unroll
        for (int i = 0; i < NPT; i++) {
            int node = ns + i * 4;
            if (node < nvalid) {
                size_t gn = (size_t)(nbase + node) * F + oc;
                d_XR[gn] = accR[i];
                d_H[gn]  = accO[i] + bb;
            }
        }
    }
}

// ---------------- kernel B: H[dst] += w_e * XR[src]  (64-wide, red.v4) ----
__global__ __launch_bounds__(256)
void k_edge1(const int* __restrict__ ei, const float* __restrict__ ew) {
    int gid = blockIdx.x * blockDim.x + threadIdx.x;   // 8 threads per edge
    int e = gid >> 3;
    int r = gid & 7;
    if (e >= N_EDGES) return;
    int src = ei[e];
    int dst = ei[N_EDGES + e];
    float w = ew[e];
    const float4* xr = reinterpret_cast<const float4*>(d_XR) + (size_t)src * 16;
    float4*       hh = reinterpret_cast<float4*>(d_H)        + (size_t)dst * 16;
    #pragma unroll
    for (int c = 0; c < 2; c++) {
        float4 v = xr[r + c * 8];
        v.x *= w; v.y *= w; v.z *= w; v.w *= w;
        unsigned long long gp = __cvta_generic_to_global(hh + r + c * 8);
        asm volatile("red.global.add.v4.f32 [%0], {%1,%2,%3,%4};"
                     :: "l"(gp), "f"(v.x), "f"(v.y), "f"(v.z), "f"(v.w)
                     : "memory");
    }
}

// ---------------- kernel C: relu + two dot products per node --------------
__global__ __launch_bounds__(256)
void k_node2() {
    int gw = (blockIdx.x * blockDim.x + threadIdx.x) >> 5;  // warp per node
    int l  = threadIdx.x & 31;
    if (gw >= N_NODES) return;
    const float* h = d_H + (size_t)gw * F;
    float h0 = fmaxf(h[l], 0.f);
    float h1 = fmaxf(h[l + 32], 0.f);
    float pa = h0 * d_vrel[l]  + h1 * d_vrel[l + 32];
    float ps = h0 * d_vroot[l] + h1 * d_vroot[l + 32];
    #pragma unroll
    for (int o = 16; o; o >>= 1) {
        pa += __shfl_xor_sync(0xffffffffu, pa, o);
        ps += __shfl_xor_sync(0xffffffffu, ps, o);
    }
    if (l == 0) { d_a[gw] = pa; d_S[gw] = ps + d_c2; }
}

// ---------------- kernel D: scalar edge pass ------------------------------
__global__ __launch_bounds__(256)
void k_edge2(const int* __restrict__ ei, const float* __restrict__ ew) {
    int e = blockIdx.x * blockDim.x + threadIdx.x;
    if (e >= N_EDGES) return;
    int src = ei[e];
    int dst = ei[N_EDGES + e];
    float v = ew[e] * d_a[src];
    atomicAdd(&d_S[dst], v);
}

// ---------------- kernel E: mean-pool bins --------------------------------
__global__ __launch_bounds__(256)
void k_pool(const int* __restrict__ batch) {
    __shared__ float sb[G];
    __shared__ float sc[G];
    int tid = threadIdx.x;
    if (tid < G) { sb[tid] = 0.f; sc[tid] = 0.f; }
    __syncthreads();
    for (int n = blockIdx.x * blockDim.x + tid; n < N_NODES;
         n += gridDim.x * blockDim.x) {
        int g = batch[n];
        atomicAdd(&sb[g], d_S[n]);
        atomicAdd(&sc[g], 1.0f);
    }
    __syncthreads();
    if (tid < G && (sb[tid] != 0.f || sc[tid] != 0.f)) {
        atomicAdd(&d_gsum[tid], sb[tid]);
        atomicAdd(&d_gcnt[tid], sc[tid]);
    }
}

// ---------------- kernel F: final output ----------------------------------
__global__ void k_final(const float* __restrict__ blin, float* __restrict__ out) {
    int g = threadIdx.x;
    if (g < G) out[g] = d_gsum[g] / fmaxf(d_gcnt[g], 1.0f) + blin[0];
}

// ---------------- launch ---------------------------------------------------
extern "C" void kernel_launch(void* const* d_in, const int* in_sizes, int n_in,
                              void* d_out, int out_size) {
    const float* x     = (const float*)d_in[0];
    const int*   ei    = (const int*)d_in[1];      // int32: JAX x64 disabled
    const float* ew    = (const float*)d_in[2];
    const int*   batch = (const int*)d_in[3];      // int32
    const float* w1rel = (const float*)d_in[4];
    const float* b1rel = (const float*)d_in[5];
    const float* w1rt  = (const float*)d_in[6];
    const float* w2rel = (const float*)d_in[7];
    const float* b2rel = (const float*)d_in[8];
    const float* w2rt  = (const float*)d_in[9];
    const float* wlin  = (const float*)d_in[10];
    const float* blin  = (const float*)d_in[11];
    float* out = (float*)d_out;

    k_init<<<1, 128>>>(w2rel, w2rt, b2rel, wlin);
    k_gemm1<<<592, 256>>>(x, w1rel, b1rel, w1rt);
    k_edge1<<<(N_EDGES * 8 + 255) / 256, 256>>>(ei, ew);
    k_node2<<<(N_NODES * 32 + 255) / 256, 256>>>();
    k_edge2<<<(N_EDGES + 255) / 256, 256>>>(ei, ew);
    k_pool<<<128, 256>>>(batch);
    k_final<<<1, 128>>>(blin, out);
}

// round 3
// speedup vs baseline: 1.0301x; 1.0301x over previous
#include <cuda_runtime.h>

#define N_NODES 100000
#define N_EDGES 1000000
#define F 64
#define G 128
#define SCANB 1024
#define NSCAN ((N_NODES + SCANB - 1) / SCANB)   // 98

// ---------------- scratch (static device globals; no allocation) ----------
__device__ __align__(16) float d_XR[(size_t)N_NODES * F];  // x @ w1_rel.T
__device__ __align__(16) float d_H [(size_t)N_NODES * F];  // x @ w1_root.T + b1 (root part only)
__device__ float d_a [N_NODES];      // relu(h1) . v_rel
__device__ float d_S [N_NODES];      // root-side scalar of layer2 + c2
__device__ float d_vrel[F];
__device__ float d_vroot[F];
__device__ float d_c2;
__device__ float d_gsum[G];
__device__ float d_gcnt[G];
// CSR by dst
__device__ int   d_deg[N_NODES];
__device__ int   d_off[N_NODES];
__device__ int   d_cursor[N_NODES];
__device__ int   d_part[128];
__device__ int   d_csrc[N_EDGES];
__device__ float d_cw  [N_EDGES];

// ---------------- zero degree histogram -----------------------------------
__global__ void k_zero() {
    int n = blockIdx.x * blockDim.x + threadIdx.x;
    if (n < N_NODES) d_deg[n] = 0;
}

// ---------------- init: collapse layer2+readout weights, zero pools -------
__global__ void k_init(const float* __restrict__ w2rel,
                       const float* __restrict__ w2root,
                       const float* __restrict__ b2,
                       const float* __restrict__ wlin) {
    int t = threadIdx.x;  // 128 threads
    if (t < G) { d_gsum[t] = 0.f; d_gcnt[t] = 0.f; }
    if (t < F) {
        float vr = 0.f, vo = 0.f;
        #pragma unroll 8
        for (int h = 0; h < F; h++) {
            float wl = wlin[h];
            vr += wl * w2rel[h * F + t];
            vo += wl * w2root[h * F + t];
        }
        d_vrel[t] = vr; d_vroot[t] = vo;
    }
    if (t == 0) {
        float c = 0.f;
        for (int h = 0; h < F; h++) c += wlin[h] * b2[h];
        d_c2 = c;
    }
}

// ---------------- kernel A: XR = x@w1_rel.T ; H = x@w1_root.T + b1 --------
#define TN 48
#define NPT 12
#define WPAD 68

__global__ __launch_bounds__(256, 4)
void k_gemm1(const float* __restrict__ x, const float* __restrict__ w1rel,
             const float* __restrict__ b1, const float* __restrict__ w1root) {
    __shared__ float sWr[F * WPAD];
    __shared__ float sWo[F * WPAD];
    __shared__ float sX[TN * F];
    __shared__ float sB1[F];

    int tid = threadIdx.x;
    for (int i = tid; i < F * F; i += 256) {
        int j = i >> 6, k = i & 63;
        sWr[j * WPAD + k] = w1rel[i];
        sWo[j * WPAD + k] = w1root[i];
    }
    if (tid < F) sB1[tid] = b1[tid];

    int oc = tid & 63;
    int ns = tid >> 6;
    float4* xs4 = reinterpret_cast<float4*>(sX);
    const int ntiles = (N_NODES + TN - 1) / TN;

    for (int tile = blockIdx.x; tile < ntiles; tile += gridDim.x) {
        int nbase  = tile * TN;
        int nvalid = min(TN, N_NODES - nbase);
        __syncthreads();
        const float4* xg = reinterpret_cast<const float4*>(x + (size_t)nbase * F);
        #pragma unroll
        for (int i = 0; i < 3; i++) {
            int idx  = tid + i * 256;
            int node = idx >> 4;
            float4 v = make_float4(0.f, 0.f, 0.f, 0.f);
            if (node < nvalid) v = xg[idx];
            xs4[idx] = v;
        }
        __syncthreads();

        float accR[NPT], accO[NPT];
        #pragma unroll
        for (int i = 0; i < NPT; i++) { accR[i] = 0.f; accO[i] = 0.f; }

        #pragma unroll
        for (int k4 = 0; k4 < 16; k4++) {
            float4 wr = *reinterpret_cast<const float4*>(&sWr[oc * WPAD + k4 * 4]);
            float4 wo = *reinterpret_cast<const float4*>(&sWo[oc * WPAD + k4 * 4]);
            #pragma unroll
            for (int i = 0; i < NPT; i++) {
                float4 xv = xs4[(ns + i * 4) * 16 + k4];
                accR[i] += xv.x * wr.x + xv.y * wr.y + xv.z * wr.z + xv.w * wr.w;
                accO[i] += xv.x * wo.x + xv.y * wo.y + xv.z * wo.z + xv.w * wo.w;
            }
        }
        float bb = sB1[oc];
        #pragma unroll
        for (int i = 0; i < NPT; i++) {
            int node = ns + i * 4;
            if (node < nvalid) {
                size_t gn = (size_t)(nbase + node) * F + oc;
                d_XR[gn] = accR[i];
                d_H[gn]  = accO[i] + bb;
            }
        }
    }
}

// ---------------- CSR build ------------------------------------------------
__global__ __launch_bounds__(256)
void k_deg(const int* __restrict__ ei) {
    int e = blockIdx.x * blockDim.x + threadIdx.x;
    if (e >= N_EDGES) return;
    atomicAdd(&d_deg[ei[N_EDGES + e]], 1);
}

__global__ void k_scanA() {     // per-block degree sums
    __shared__ int s[SCANB];
    int tid = threadIdx.x;
    int n = blockIdx.x * SCANB + tid;
    s[tid] = (n < N_NODES) ? d_deg[n] : 0;
    __syncthreads();
    for (int o = SCANB / 2; o; o >>= 1) {
        if (tid < o) s[tid] += s[tid + o];
        __syncthreads();
    }
    if (tid == 0) d_part[blockIdx.x] = s[0];
}

__global__ void k_scanB() {     // serial exclusive scan of 98 partials
    if (threadIdx.x == 0) {
        int acc = 0;
        for (int i = 0; i < NSCAN; i++) { int t = d_part[i]; d_part[i] = acc; acc += t; }
    }
}

__global__ void k_scanC() {     // intra-block exclusive scan + base
    __shared__ int s[SCANB];
    int tid = threadIdx.x;
    int n = blockIdx.x * SCANB + tid;
    int v = (n < N_NODES) ? d_deg[n] : 0;
    s[tid] = v;
    __syncthreads();
    for (int o = 1; o < SCANB; o <<= 1) {
        int t = (tid >= o) ? s[tid - o] : 0;
        __syncthreads();
        s[tid] += t;
        __syncthreads();
    }
    if (n < N_NODES) {
        int off = d_part[blockIdx.x] + s[tid] - v;
        d_off[n] = off;
        d_cursor[n] = off;
    }
}

__global__ __launch_bounds__(256)
void k_fill(const int* __restrict__ ei, const float* __restrict__ ew) {
    int e = blockIdx.x * blockDim.x + threadIdx.x;
    if (e >= N_EDGES) return;
    int src = ei[e];
    int dst = ei[N_EDGES + e];
    int slot = atomicAdd(&d_cursor[dst], 1);
    d_csrc[slot] = src;
    d_cw[slot]   = ew[e];
}

// ---- aggr: warp per node. h1 = Hroot + sum_e w*XR[src]; relu; two dots ---
__global__ __launch_bounds__(256)
void k_aggr() {
    int node = (blockIdx.x * blockDim.x + threadIdx.x) >> 5;
    int l    = threadIdx.x & 31;
    if (node >= N_NODES) return;
    int beg = d_off[node];
    int deg = d_deg[node];
    float a0 = 0.f, a1 = 0.f;
    // software pipeline: prefetch next edge's (src, w)
    int   src = (deg > 0) ? d_csrc[beg] : 0;
    float w   = (deg > 0) ? d_cw[beg]   : 0.f;
    for (int j = 0; j < deg; j++) {
        int   nsrc = (j + 1 < deg) ? d_csrc[beg + j + 1] : 0;
        float nw   = (j + 1 < deg) ? d_cw[beg + j + 1]   : 0.f;
        const float* xr = d_XR + (size_t)src * F;
        a0 = fmaf(w, xr[l],      a0);
        a1 = fmaf(w, xr[l + 32], a1);
        src = nsrc; w = nw;
    }
    const float* h = d_H + (size_t)node * F;
    float h0 = fmaxf(h[l]      + a0, 0.f);
    float h1 = fmaxf(h[l + 32] + a1, 0.f);
    float pa = h0 * d_vrel[l]  + h1 * d_vrel[l + 32];
    float ps = h0 * d_vroot[l] + h1 * d_vroot[l + 32];
    #pragma unroll
    for (int o = 16; o; o >>= 1) {
        pa += __shfl_xor_sync(0xffffffffu, pa, o);
        ps += __shfl_xor_sync(0xffffffffu, ps, o);
    }
    if (l == 0) { d_a[node] = pa; d_S[node] = ps + d_c2; }
}

// ---- layer2 scalar aggregation (gather via CSR) + mean-pool bins ---------
__global__ __launch_bounds__(256)
void k_scalar_pool(const int* __restrict__ batch) {
    __shared__ float sb[G];
    __shared__ float sc[G];
    int tid = threadIdx.x;
    if (tid < G) { sb[tid] = 0.f; sc[tid] = 0.f; }
    __syncthreads();
    int n = blockIdx.x * blockDim.x + tid;
    if (n < N_NODES) {
        int beg = d_off[n];
        int deg = d_deg[n];
        float s = 0.f;
        for (int j = 0; j < deg; j++)
            s = fmaf(d_cw[beg + j], d_a[d_csrc[beg + j]], s);
        float S = d_S[n] + s;
        int b = batch[n];
        atomicAdd(&sb[b], S);
        atomicAdd(&sc[b], 1.0f);
    }
    __syncthreads();
    if (tid < G && (sb[tid] != 0.f || sc[tid] != 0.f)) {
        atomicAdd(&d_gsum[tid], sb[tid]);
        atomicAdd(&d_gcnt[tid], sc[tid]);
    }
}

// ---------------- final ----------------------------------------------------
__global__ void k_final(const float* __restrict__ blin, float* __restrict__ out) {
    int g = threadIdx.x;
    if (g < G) out[g] = d_gsum[g] / fmaxf(d_gcnt[g], 1.0f) + blin[0];
}

// ---------------- launch ---------------------------------------------------
extern "C" void kernel_launch(void* const* d_in, const int* in_sizes, int n_in,
                              void* d_out, int out_size) {
    const float* x     = (const float*)d_in[0];
    const int*   ei    = (const int*)d_in[1];
    const float* ew    = (const float*)d_in[2];
    const int*   batch = (const int*)d_in[3];
    const float* w1rel = (const float*)d_in[4];
    const float* b1rel = (const float*)d_in[5];
    const float* w1rt  = (const float*)d_in[6];
    const float* w2rel = (const float*)d_in[7];
    const float* b2rel = (const float*)d_in[8];
    const float* w2rt  = (const float*)d_in[9];
    const float* wlin  = (const float*)d_in[10];
    const float* blin  = (const float*)d_in[11];
    float* out = (float*)d_out;

    k_zero<<<NSCAN, SCANB>>>();
    k_init<<<1, 128>>>(w2rel, w2rt, b2rel, wlin);
    k_deg<<<(N_EDGES + 255) / 256, 256>>>(ei);
    k_gemm1<<<592, 256>>>(x, w1rel, b1rel, w1rt);
    k_scanA<<<NSCAN, SCANB>>>();
    k_scanB<<<1, 32>>>();
    k_scanC<<<NSCAN, SCANB>>>();
    k_fill<<<(N_EDGES + 255) / 256, 256>>>(ei, ew);
    k_aggr<<<(N_NODES * 32 + 255) / 256, 256>>>();
    k_scalar_pool<<<(N_NODES + 255) / 256, 256>>>(batch);
    k_final<<<1, 128>>>(blin, out);
}